// round 2
// baseline (speedup 1.0000x reference)
#include <cuda_runtime.h>
#include <math.h>

#define MAXN 100000
#define MAXE 1600000
#define MAXEP (MAXN + MAXE)
#define FD 64
#define BN_EPS 1e-5f
#define ATT_SLOPE 0.2f
#define ACT_SLOPE 0.01f

// ---------------- static device scratch (no allocations allowed) ----------------
__device__ float g_h[(size_t)MAXN * FD];     // transformed features (layer1, then layer2)
__device__ float g_agg[(size_t)MAXN * FD];   // layer-1 aggregation output (pre-BN)
__device__ float g_ssrc[MAXN];
__device__ float g_sdst[MAXN];
__device__ int   g_deg[MAXN];
__device__ int   g_rowptr[MAXN + 1];
__device__ int   g_cursor[MAXN];
__device__ int   g_csrsrc[MAXEP];
__device__ float g_bnacc[2 * FD];

#define SCAN_BS 512
#define NBLK_MAX ((MAXN + SCAN_BS - 1) / SCAN_BS)
__device__ int g_bsum[NBLK_MAX];

// ---------------- CSR build ----------------
__global__ void zero_kernel(int n) {
    int i = blockIdx.x * blockDim.x + threadIdx.x;
    if (i < n) g_deg[i] = 0;
    if (i < 2 * FD) g_bnacc[i] = 0.0f;
}

__global__ void count_kernel(const int* __restrict__ ei, int e, int n) {
    int i = blockIdx.x * blockDim.x + threadIdx.x;
    int tot = e + n;
    if (i >= tot) return;
    int d = (i < e) ? ei[e + i] : (i - e);
    atomicAdd(&g_deg[d], 1);
}

__global__ void scan1_kernel(int n) {
    __shared__ int sh[SCAN_BS];
    int tid = threadIdx.x;
    int idx = blockIdx.x * SCAN_BS + tid;
    int v = (idx < n) ? g_deg[idx] : 0;
    sh[tid] = v;
    __syncthreads();
    for (int off = 1; off < SCAN_BS; off <<= 1) {
        int t = (tid >= off) ? sh[tid - off] : 0;
        __syncthreads();
        sh[tid] += t;
        __syncthreads();
    }
    if (idx < n) g_rowptr[idx] = sh[tid] - v;  // exclusive within block
    if (tid == SCAN_BS - 1) g_bsum[blockIdx.x] = sh[tid];
}

__global__ void scan2_kernel(int nb, int n) {
    __shared__ int sh[SCAN_BS];
    int tid = threadIdx.x;
    int v = (tid < nb) ? g_bsum[tid] : 0;
    sh[tid] = v;
    __syncthreads();
    for (int off = 1; off < SCAN_BS; off <<= 1) {
        int t = (tid >= off) ? sh[tid - off] : 0;
        __syncthreads();
        sh[tid] += t;
        __syncthreads();
    }
    if (tid < nb) g_bsum[tid] = sh[tid] - v;  // exclusive block offsets
    if (tid == nb - 1) g_rowptr[n] = sh[tid]; // total
}

__global__ void scan3_kernel(int n) {
    int i = blockIdx.x * blockDim.x + threadIdx.x;
    if (i >= n) return;
    int r = g_rowptr[i] + g_bsum[i / SCAN_BS];
    g_rowptr[i] = r;
    g_cursor[i] = r;
}

__global__ void fill_kernel(const int* __restrict__ ei, int e, int n) {
    int i = blockIdx.x * blockDim.x + threadIdx.x;
    int tot = e + n;
    if (i >= tot) return;
    int s, d;
    if (i < e) { s = ei[i]; d = ei[e + i]; }
    else       { s = i - e; d = i - e; }
    int p = atomicAdd(&g_cursor[d], 1);
    g_csrsrc[p] = s;
}

// ---------------- GEMM: H = X @ W (with optional fused BN+LeakyReLU on X) ----------------
// Also computes ssrc = H @ a_src, sdst = H @ a_dst per row.
// Block: 256 threads, 16 rows x 64 cols per block. Thread t: row t>>4, cols 4*(t&15)..+3.
__global__ void gemm_kernel(const float* __restrict__ X, const float* __restrict__ W,
                            const float* __restrict__ a_src, const float* __restrict__ a_dst,
                            float* __restrict__ H, float* __restrict__ ssrc, float* __restrict__ sdst,
                            int n, int apply_bn,
                            const float* __restrict__ bng, const float* __restrict__ bnb) {
    __shared__ float Ws[FD * FD];
    __shared__ float xs[16][FD + 1];
    __shared__ float as[FD], ad[FD], sc[FD], shf[FD];

    int tid = threadIdx.x;
    // load W
    for (int i = tid; i < FD * FD / 4; i += 256)
        ((float4*)Ws)[i] = ((const float4*)W)[i];
    if (tid < FD) {
        as[tid] = a_src[tid];
        ad[tid] = a_dst[tid];
        if (apply_bn) {
            float invn = 1.0f / (float)n;
            float mean = g_bnacc[tid] * invn;
            float var  = g_bnacc[FD + tid] * invn - mean * mean;
            float istd = rsqrtf(var + BN_EPS);
            float s = istd * bng[tid];
            sc[tid]  = s;
            shf[tid] = bnb[tid] - mean * s;
        }
    }
    __syncthreads();

    int row0 = blockIdx.x * 16;
    for (int i = tid; i < 16 * FD; i += 256) {
        int lr = i >> 6, c = i & 63;
        int gr = row0 + lr;
        float v = (gr < n) ? X[(size_t)gr * FD + c] : 0.0f;
        if (apply_bn) {
            v = v * sc[c] + shf[c];
            v = (v > 0.0f) ? v : ACT_SLOPE * v;
        }
        xs[lr][c] = v;
    }
    __syncthreads();

    int r = tid >> 4;
    int c4 = (tid & 15) * 4;
    float4 acc = make_float4(0.f, 0.f, 0.f, 0.f);
#pragma unroll
    for (int k = 0; k < FD; k++) {
        float xk = xs[r][k];
        float4 wv = *(const float4*)&Ws[k * FD + c4];
        acc.x += xk * wv.x; acc.y += xk * wv.y;
        acc.z += xk * wv.z; acc.w += xk * wv.w;
    }
    int row = row0 + r;
    if (row < n)
        *(float4*)&H[(size_t)row * FD + c4] = acc;

    float ps = acc.x * as[c4] + acc.y * as[c4 + 1] + acc.z * as[c4 + 2] + acc.w * as[c4 + 3];
    float pd = acc.x * ad[c4] + acc.y * ad[c4 + 1] + acc.z * ad[c4 + 2] + acc.w * ad[c4 + 3];
#pragma unroll
    for (int o = 8; o; o >>= 1) {
        ps += __shfl_down_sync(0xffffffffu, ps, o, 16);
        pd += __shfl_down_sync(0xffffffffu, pd, o, 16);
    }
    if ((tid & 15) == 0 && row < n) {
        ssrc[row] = ps;
        sdst[row] = pd;
    }
}

// ---------------- Aggregation: warp per destination node, CSR, no atomics ----------------
__global__ void agg_kernel(const float* __restrict__ H,
                           const float* __restrict__ ssrc, const float* __restrict__ sdst,
                           const float* __restrict__ bias,
                           const float* __restrict__ x0,  // residual input (may be null)
                           float* __restrict__ out, int n, int residual) {
    int warp = (blockIdx.x * blockDim.x + threadIdx.x) >> 5;
    int lane = threadIdx.x & 31;
    if (warp >= n) return;
    int node = warp;
    int start = g_rowptr[node];
    int end   = g_rowptr[node + 1];
    float sd = sdst[node];

    // pass 1: max logit
    float mx = -3.4e38f;
    for (int t = start + lane; t < end; t += 32) {
        int s = g_csrsrc[t];
        float lg = ssrc[s] + sd;
        lg = (lg > 0.0f) ? lg : ATT_SLOPE * lg;
        mx = fmaxf(mx, lg);
    }
#pragma unroll
    for (int o = 16; o; o >>= 1) mx = fmaxf(mx, __shfl_xor_sync(0xffffffffu, mx, o));

    // pass 2: exp, sum, weighted accumulation (unnormalized, divide by z at end)
    float z = 0.0f;
    float2 acc = make_float2(0.f, 0.f);
    const float2* H2 = (const float2*)H;
    for (int base = start; base < end; base += 32) {
        int t = base + lane;
        int s = 0;
        float e = 0.0f;
        if (t < end) {
            s = g_csrsrc[t];
            float lg = ssrc[s] + sd;
            lg = (lg > 0.0f) ? lg : ATT_SLOPE * lg;
            e = __expf(lg - mx);
        }
        z += e;
        int cnt = min(32, end - base);
        for (int j = 0; j < cnt; j++) {
            int   sj = __shfl_sync(0xffffffffu, s, j);
            float ej = __shfl_sync(0xffffffffu, e, j);
            float2 hv = __ldg(&H2[(size_t)sj * 32 + lane]);
            acc.x += ej * hv.x;
            acc.y += ej * hv.y;
        }
    }
#pragma unroll
    for (int o = 16; o; o >>= 1) z += __shfl_xor_sync(0xffffffffu, z, o);

    float inv = 1.0f / z;
    float2 b = ((const float2*)bias)[lane];
    float2 r;
    r.x = acc.x * inv + b.x;
    r.y = acc.y * inv + b.y;
    if (residual) {
        float2 xv = ((const float2*)x0)[(size_t)node * 32 + lane];
        r.x = 0.5f * (xv.x + r.x);
        r.y = 0.5f * (xv.y + r.y);
    }
    ((float2*)out)[(size_t)node * 32 + lane] = r;
}

// ---------------- BN statistics: per-column sum and sumsq ----------------
__global__ void bnstats_kernel(const float* __restrict__ A, int n) {
    __shared__ float s1[256], s2[256];
    int tid = threadIdx.x;
    int c = tid & 63;
    int q = tid >> 6;             // 0..3
    float sum = 0.f, sq = 0.f;
    int row0 = blockIdx.x * 64;
    for (int rr = q; rr < 64; rr += 4) {
        int row = row0 + rr;
        if (row < n) {
            float v = A[(size_t)row * FD + c];
            sum += v;
            sq  += v * v;
        }
    }
    s1[tid] = sum; s2[tid] = sq;
    __syncthreads();
    if (q == 0) {
        sum = s1[c] + s1[64 + c] + s1[128 + c] + s1[192 + c];
        sq  = s2[c] + s2[64 + c] + s2[128 + c] + s2[192 + c];
        atomicAdd(&g_bnacc[c], sum);
        atomicAdd(&g_bnacc[FD + c], sq);
    }
}

// ---------------- launch ----------------
extern "C" void kernel_launch(void* const* d_in, const int* in_sizes, int n_in,
                              void* d_out, int out_size) {
    const float* x        = (const float*)d_in[0];
    const float* W1       = (const float*)d_in[1];
    const float* att_src1 = (const float*)d_in[2];
    const float* att_dst1 = (const float*)d_in[3];
    const float* bias1    = (const float*)d_in[4];
    const float* bn_gamma = (const float*)d_in[5];
    const float* bn_beta  = (const float*)d_in[6];
    const float* W2       = (const float*)d_in[7];
    const float* att_src2 = (const float*)d_in[8];
    const float* att_dst2 = (const float*)d_in[9];
    const float* bias2    = (const float*)d_in[10];
    const int*   ei       = (const int*)d_in[11];

    int n = in_sizes[0] / FD;      // nodes
    int e = in_sizes[11] / 2;      // edges (before self-loops)
    int tot = e + n;

    float* out = (float*)d_out;

    // device-symbol pointers usable from host launches (device globals referenced in kernels)
    float* d_h    = nullptr;
    float* d_agg  = nullptr;
    float* d_ssrc = nullptr;
    float* d_sdst = nullptr;
    cudaGetSymbolAddress((void**)&d_h, g_h);
    cudaGetSymbolAddress((void**)&d_agg, g_agg);
    cudaGetSymbolAddress((void**)&d_ssrc, g_ssrc);
    cudaGetSymbolAddress((void**)&d_sdst, g_sdst);

    int nb = (n + SCAN_BS - 1) / SCAN_BS;

    // --- CSR build (shared by both layers) ---
    zero_kernel<<<(n + 255) / 256, 256>>>(n);
    count_kernel<<<(tot + 255) / 256, 256>>>(ei, e, n);
    scan1_kernel<<<nb, SCAN_BS>>>(n);
    scan2_kernel<<<1, SCAN_BS>>>(nb, n);
    scan3_kernel<<<(n + 255) / 256, 256>>>(n);
    fill_kernel<<<(tot + 255) / 256, 256>>>(ei, e, n);

    int gemm_grid = (n + 15) / 16;
    int agg_grid  = (n + 7) / 8;   // 8 warps / block

    // --- Layer 1 ---
    gemm_kernel<<<gemm_grid, 256>>>(x, W1, att_src1, att_dst1,
                                    d_h, d_ssrc, d_sdst, n, 0, nullptr, nullptr);
    agg_kernel<<<agg_grid, 256>>>(d_h, d_ssrc, d_sdst, bias1, nullptr, d_agg, n, 0);

    // --- BN stats ---
    bnstats_kernel<<<(n + 63) / 64, 256>>>(d_agg, n);

    // --- Layer 2 (BN + LeakyReLU fused into GEMM input) ---
    gemm_kernel<<<gemm_grid, 256>>>(d_agg, W2, att_src2, att_dst2,
                                    d_h, d_ssrc, d_sdst, n, 1, bn_gamma, bn_beta);
    agg_kernel<<<agg_grid, 256>>>(d_h, d_ssrc, d_sdst, bias2, x, out, n, 1);
}

// round 3
// speedup vs baseline: 1.9529x; 1.9529x over previous
#include <cuda_runtime.h>
#include <math.h>

#define MAXN 100000
#define MAXE 1600000
#define MAXEP (MAXN + MAXE)
#define FD 64
#define BN_EPS 1e-5f
#define ATT_SLOPE 0.2f
#define ACT_SLOPE 0.01f

// ---------------- static device scratch ----------------
__device__ float g_h[(size_t)MAXN * FD];
__device__ float g_agg[(size_t)MAXN * FD];
__device__ float g_ssrc[MAXN];
__device__ float g_sdst[MAXN];
__device__ int   g_deg[MAXN];
__device__ int   g_rowptr[MAXN + 1];
__device__ int   g_cursor[MAXN];
__device__ int   g_csrsrc[MAXEP];
__device__ float g_bnacc[2 * FD];
__device__ int   g_maxbits[4];   // [2*li] = max(0,ssrc), [2*li+1] = max(0,sdst) as int bits

#define SCAN_BS 512
#define NBLK_MAX ((MAXN + SCAN_BS - 1) / SCAN_BS)
__device__ int g_bsum[NBLK_MAX];

// ---------------- CSR build ----------------
__global__ void zero_kernel(int n) {
    int i = blockIdx.x * blockDim.x + threadIdx.x;
    if (i < n) g_deg[i] = 0;
    if (i < 2 * FD) g_bnacc[i] = 0.0f;
    if (i < 4) g_maxbits[i] = 0;   // float 0.0f bits
}

__global__ void count_kernel(const int* __restrict__ ei, int e, int n) {
    int i = blockIdx.x * blockDim.x + threadIdx.x;
    int tot = e + n;
    if (i >= tot) return;
    int d = (i < e) ? ei[e + i] : (i - e);
    atomicAdd(&g_deg[d], 1);
}

__global__ void scan1_kernel(int n) {
    __shared__ int sh[SCAN_BS];
    int tid = threadIdx.x;
    int idx = blockIdx.x * SCAN_BS + tid;
    int v = (idx < n) ? g_deg[idx] : 0;
    sh[tid] = v;
    __syncthreads();
    for (int off = 1; off < SCAN_BS; off <<= 1) {
        int t = (tid >= off) ? sh[tid - off] : 0;
        __syncthreads();
        sh[tid] += t;
        __syncthreads();
    }
    if (idx < n) g_rowptr[idx] = sh[tid] - v;
    if (tid == SCAN_BS - 1) g_bsum[blockIdx.x] = sh[tid];
}

__global__ void scan2_kernel(int nb, int n) {
    __shared__ int sh[SCAN_BS];
    int tid = threadIdx.x;
    int v = (tid < nb) ? g_bsum[tid] : 0;
    sh[tid] = v;
    __syncthreads();
    for (int off = 1; off < SCAN_BS; off <<= 1) {
        int t = (tid >= off) ? sh[tid - off] : 0;
        __syncthreads();
        sh[tid] += t;
        __syncthreads();
    }
    if (tid < nb) g_bsum[tid] = sh[tid] - v;
    if (tid == nb - 1) g_rowptr[n] = sh[tid];
}

__global__ void scan3_kernel(int n) {
    int i = blockIdx.x * blockDim.x + threadIdx.x;
    if (i >= n) return;
    int r = g_rowptr[i] + g_bsum[i / SCAN_BS];
    g_rowptr[i] = r;
    g_cursor[i] = r;
}

__global__ void fill_kernel(const int* __restrict__ ei, int e, int n) {
    int i = blockIdx.x * blockDim.x + threadIdx.x;
    int tot = e + n;
    if (i >= tot) return;
    int s, d;
    if (i < e) { s = ei[i]; d = ei[e + i]; }
    else       { s = i - e; d = i - e; }
    int p = atomicAdd(&g_cursor[d], 1);
    g_csrsrc[p] = s;
}

// ---------------- GEMM: H = X @ W, register-tiled 4x4, fused scores + global max ----------------
// Block: 256 threads -> 64 rows x 64 cols. Thread (ty=tid>>4, tx=tid&15): rows ty*4..+3, cols tx*4..+3.
__global__ void gemm_kernel(const float* __restrict__ X, const float* __restrict__ W,
                            const float* __restrict__ a_src, const float* __restrict__ a_dst,
                            float* __restrict__ H, float* __restrict__ ssrc, float* __restrict__ sdst,
                            int n, int apply_bn,
                            const float* __restrict__ bng, const float* __restrict__ bnb, int li) {
    __shared__ float Ws[FD * FD];
    __shared__ float xs[64][FD + 4];
    __shared__ float as[FD], ad[FD], sc[FD], shf[FD];
    __shared__ float wmaxS[8], wmaxD[8];

    int tid = threadIdx.x;
    for (int i = tid; i < FD * FD / 4; i += 256)
        ((float4*)Ws)[i] = ((const float4*)W)[i];
    if (tid < FD) {
        as[tid] = a_src[tid];
        ad[tid] = a_dst[tid];
        if (apply_bn) {
            float invn = 1.0f / (float)n;
            float mean = g_bnacc[tid] * invn;
            float var  = g_bnacc[FD + tid] * invn - mean * mean;
            float istd = rsqrtf(var + BN_EPS);
            float s = istd * bng[tid];
            sc[tid]  = s;
            shf[tid] = bnb[tid] - mean * s;
        }
    }
    __syncthreads();

    int row0 = blockIdx.x * 64;
    // load 64 rows x 64 cols of X (optionally BN+LeakyReLU) into xs
    for (int i = tid; i < 64 * FD / 4; i += 256) {
        int lr = i >> 4;          // 16 float4 per row
        int c4 = (i & 15) * 4;
        int gr = row0 + lr;
        float4 v = make_float4(0.f, 0.f, 0.f, 0.f);
        if (gr < n) v = ((const float4*)X)[(size_t)gr * 16 + (i & 15)];
        if (apply_bn) {
            v.x = v.x * sc[c4]     + shf[c4];
            v.y = v.y * sc[c4 + 1] + shf[c4 + 1];
            v.z = v.z * sc[c4 + 2] + shf[c4 + 2];
            v.w = v.w * sc[c4 + 3] + shf[c4 + 3];
            v.x = (v.x > 0.f) ? v.x : ACT_SLOPE * v.x;
            v.y = (v.y > 0.f) ? v.y : ACT_SLOPE * v.y;
            v.z = (v.z > 0.f) ? v.z : ACT_SLOPE * v.z;
            v.w = (v.w > 0.f) ? v.w : ACT_SLOPE * v.w;
        }
        *(float4*)&xs[lr][c4] = v;
    }
    __syncthreads();

    int ty = tid >> 4, tx = tid & 15;
    int r0 = ty * 4, c0 = tx * 4;
    float acc[4][4];
#pragma unroll
    for (int i = 0; i < 4; i++)
#pragma unroll
        for (int j = 0; j < 4; j++) acc[i][j] = 0.f;

#pragma unroll 16
    for (int k = 0; k < FD; k++) {
        float4 wv = *(const float4*)&Ws[k * FD + c0];
        float x0 = xs[r0][k], x1 = xs[r0 + 1][k], x2 = xs[r0 + 2][k], x3 = xs[r0 + 3][k];
        acc[0][0] += x0 * wv.x; acc[0][1] += x0 * wv.y; acc[0][2] += x0 * wv.z; acc[0][3] += x0 * wv.w;
        acc[1][0] += x1 * wv.x; acc[1][1] += x1 * wv.y; acc[1][2] += x1 * wv.z; acc[1][3] += x1 * wv.w;
        acc[2][0] += x2 * wv.x; acc[2][1] += x2 * wv.y; acc[2][2] += x2 * wv.z; acc[2][3] += x2 * wv.w;
        acc[3][0] += x3 * wv.x; acc[3][1] += x3 * wv.y; acc[3][2] += x3 * wv.z; acc[3][3] += x3 * wv.w;
    }

    // store H + compute per-row score partials
    float lmS = 0.f, lmD = 0.f;
#pragma unroll
    for (int i = 0; i < 4; i++) {
        int row = row0 + r0 + i;
        if (row < n)
            *(float4*)&H[(size_t)row * FD + c0] =
                make_float4(acc[i][0], acc[i][1], acc[i][2], acc[i][3]);
        float ps = acc[i][0] * as[c0] + acc[i][1] * as[c0 + 1] + acc[i][2] * as[c0 + 2] + acc[i][3] * as[c0 + 3];
        float pd = acc[i][0] * ad[c0] + acc[i][1] * ad[c0 + 1] + acc[i][2] * ad[c0 + 2] + acc[i][3] * ad[c0 + 3];
#pragma unroll
        for (int o = 8; o; o >>= 1) {
            ps += __shfl_down_sync(0xffffffffu, ps, o, 16);
            pd += __shfl_down_sync(0xffffffffu, pd, o, 16);
        }
        if (tx == 0 && row < n) {
            ssrc[row] = ps;
            sdst[row] = pd;
            lmS = fmaxf(lmS, ps);
            lmD = fmaxf(lmD, pd);
        }
    }
    // block-level max for numeric shift M (upper bound; lmS/lmD >= 0)
#pragma unroll
    for (int o = 16; o; o >>= 1) {
        lmS = fmaxf(lmS, __shfl_xor_sync(0xffffffffu, lmS, o));
        lmD = fmaxf(lmD, __shfl_xor_sync(0xffffffffu, lmD, o));
    }
    int wid = tid >> 5;
    if ((tid & 31) == 0) { wmaxS[wid] = lmS; wmaxD[wid] = lmD; }
    __syncthreads();
    if (tid == 0) {
        float mS = 0.f, mD = 0.f;
#pragma unroll
        for (int w = 0; w < 8; w++) { mS = fmaxf(mS, wmaxS[w]); mD = fmaxf(mD, wmaxD[w]); }
        atomicMax(&g_maxbits[2 * li],     __float_as_int(mS));  // non-negative floats: int order == float order
        atomicMax(&g_maxbits[2 * li + 1], __float_as_int(mD));
    }
}

// ---------------- Aggregation: warp per dst node, single pass, dual-edge float4 ----------------
__global__ void agg_kernel(const float* __restrict__ H,
                           const float* __restrict__ ssrc, const float* __restrict__ sdst,
                           const float* __restrict__ bias,
                           const float* __restrict__ x0,
                           float* __restrict__ out, int n, int residual, int li) {
    int warp = (blockIdx.x * blockDim.x + threadIdx.x) >> 5;
    int lane = threadIdx.x & 31;
    if (warp >= n) return;
    float M = __int_as_float(g_maxbits[2 * li]) + __int_as_float(g_maxbits[2 * li + 1]);
    int start = g_rowptr[warp];
    int end   = g_rowptr[warp + 1];
    float sd = sdst[warp];
    int half = lane >> 4, sub = lane & 15;

    float z = 0.0f;
    float4 acc = make_float4(0.f, 0.f, 0.f, 0.f);
    const float4* H4 = (const float4*)H;

    for (int base = start; base < end; base += 32) {
        int t = base + lane;
        int s = 0;
        float e = 0.0f;
        if (t < end) {
            s = g_csrsrc[t];
            float lg = ssrc[s] + sd;
            lg = (lg > 0.0f) ? lg : ATT_SLOPE * lg;
            e = __expf(lg - M);
        }
        z += e;
        int cnt = min(32, end - base);
        int cnt2 = (cnt + 1) & ~1;
#pragma unroll 2
        for (int j = 0; j < cnt2; j += 2) {
            int idx = j + half;                      // half 0 -> even edges, half 1 -> odd edges
            int   sj = __shfl_sync(0xffffffffu, s, idx);
            float ej = __shfl_sync(0xffffffffu, e, idx);
            float4 hv = __ldg(&H4[(size_t)sj * 16 + sub]);
            acc.x += ej * hv.x;
            acc.y += ej * hv.y;
            acc.z += ej * hv.z;
            acc.w += ej * hv.w;
        }
    }
    // combine the two halves (same columns in both halves)
    acc.x += __shfl_xor_sync(0xffffffffu, acc.x, 16);
    acc.y += __shfl_xor_sync(0xffffffffu, acc.y, 16);
    acc.z += __shfl_xor_sync(0xffffffffu, acc.z, 16);
    acc.w += __shfl_xor_sync(0xffffffffu, acc.w, 16);
#pragma unroll
    for (int o = 16; o; o >>= 1) z += __shfl_xor_sync(0xffffffffu, z, o);

    if (half == 0) {
        float inv = 1.0f / z;
        float4 b = ((const float4*)bias)[sub];
        float4 r;
        r.x = acc.x * inv + b.x;
        r.y = acc.y * inv + b.y;
        r.z = acc.z * inv + b.z;
        r.w = acc.w * inv + b.w;
        if (residual) {
            float4 xv = ((const float4*)x0)[(size_t)warp * 16 + sub];
            r.x = 0.5f * (xv.x + r.x);
            r.y = 0.5f * (xv.y + r.y);
            r.z = 0.5f * (xv.z + r.z);
            r.w = 0.5f * (xv.w + r.w);
        }
        ((float4*)out)[(size_t)warp * 16 + sub] = r;
    }
}

// ---------------- BN statistics ----------------
__global__ void bnstats_kernel(const float* __restrict__ A, int n) {
    __shared__ float s1[256], s2[256];
    int tid = threadIdx.x;
    int c = tid & 63;
    int q = tid >> 6;
    float sum = 0.f, sq = 0.f;
    int row0 = blockIdx.x * 64;
    for (int rr = q; rr < 64; rr += 4) {
        int row = row0 + rr;
        if (row < n) {
            float v = A[(size_t)row * FD + c];
            sum += v;
            sq  += v * v;
        }
    }
    s1[tid] = sum; s2[tid] = sq;
    __syncthreads();
    if (q == 0) {
        sum = s1[c] + s1[64 + c] + s1[128 + c] + s1[192 + c];
        sq  = s2[c] + s2[64 + c] + s2[128 + c] + s2[192 + c];
        atomicAdd(&g_bnacc[c], sum);
        atomicAdd(&g_bnacc[FD + c], sq);
    }
}

// ---------------- launch ----------------
extern "C" void kernel_launch(void* const* d_in, const int* in_sizes, int n_in,
                              void* d_out, int out_size) {
    const float* x        = (const float*)d_in[0];
    const float* W1       = (const float*)d_in[1];
    const float* att_src1 = (const float*)d_in[2];
    const float* att_dst1 = (const float*)d_in[3];
    const float* bias1    = (const float*)d_in[4];
    const float* bn_gamma = (const float*)d_in[5];
    const float* bn_beta  = (const float*)d_in[6];
    const float* W2       = (const float*)d_in[7];
    const float* att_src2 = (const float*)d_in[8];
    const float* att_dst2 = (const float*)d_in[9];
    const float* bias2    = (const float*)d_in[10];
    const int*   ei       = (const int*)d_in[11];

    int n = in_sizes[0] / FD;
    int e = in_sizes[11] / 2;
    int tot = e + n;

    float* out = (float*)d_out;

    float* d_h    = nullptr;
    float* d_agg  = nullptr;
    float* d_ssrc = nullptr;
    float* d_sdst = nullptr;
    cudaGetSymbolAddress((void**)&d_h, g_h);
    cudaGetSymbolAddress((void**)&d_agg, g_agg);
    cudaGetSymbolAddress((void**)&d_ssrc, g_ssrc);
    cudaGetSymbolAddress((void**)&d_sdst, g_sdst);

    int nb = (n + SCAN_BS - 1) / SCAN_BS;

    // --- CSR build ---
    zero_kernel<<<(n + 255) / 256, 256>>>(n);
    count_kernel<<<(tot + 255) / 256, 256>>>(ei, e, n);
    scan1_kernel<<<nb, SCAN_BS>>>(n);
    scan2_kernel<<<1, SCAN_BS>>>(nb, n);
    scan3_kernel<<<(n + 255) / 256, 256>>>(n);
    fill_kernel<<<(tot + 255) / 256, 256>>>(ei, e, n);

    int gemm_grid = (n + 63) / 64;
    int agg_grid  = (n + 7) / 8;

    // --- Layer 1 ---
    gemm_kernel<<<gemm_grid, 256>>>(x, W1, att_src1, att_dst1,
                                    d_h, d_ssrc, d_sdst, n, 0, nullptr, nullptr, 0);
    agg_kernel<<<agg_grid, 256>>>(d_h, d_ssrc, d_sdst, bias1, nullptr, d_agg, n, 0, 0);

    // --- BN stats ---
    bnstats_kernel<<<(n + 63) / 64, 256>>>(d_agg, n);

    // --- Layer 2 ---
    gemm_kernel<<<gemm_grid, 256>>>(d_agg, W2, att_src2, att_dst2,
                                    d_h, d_ssrc, d_sdst, n, 1, bn_gamma, bn_beta, 1);
    agg_kernel<<<agg_grid, 256>>>(d_h, d_ssrc, d_sdst, bias2, x, out, n, 1, 1);
}